// round 10
// baseline (speedup 1.0000x reference)
#include <cuda_runtime.h>

// inputs [4,320,320,2] f32 -> output [4,320,320,6] f32
#define NB   4
#define NH   320
#define NW   320

// Scratch: interleaved squared 1D column distances, [b][h][w]{ch0,ch1}.
__device__ float2 g2_scratch2[NB * NH * NW];

// -------------------------------------------------------------------------
// Kernel 1: column pass, segmented, BOTH channels per thread (input channel
// pair is contiguous -> one float2 load per row).
// grid (NB, NW/32), block (32, 10): 32 columns x 10 row-segments of 32.
// Sentinels (-32768 / 20000) give g^2 >= 4e8: exp underflows to exactly 0
// for all sigmas and can never beat a real candidate -> matches BIG=1e5.
// -------------------------------------------------------------------------
#define CW   32
#define NSEG 10
#define SEGH 32

__global__ void __launch_bounds__(CW * NSEG) col_pass_kernel(const float2* __restrict__ in2) {
    __shared__ short sL0[NH][CW];         // 20 KB
    __shared__ short sL1[NH][CW];         // 20 KB
    __shared__ short segLast[2][NSEG][CW];
    __shared__ short segFirst[2][NSEG][CW];
    __shared__ short incLast[2][NSEG][CW];
    __shared__ short incNxt[2][NSEG][CW];

    const int b   = blockIdx.x;
    const int wt  = threadIdx.x;          // 0..31
    const int seg = threadIdx.y;          // 0..9
    const int w   = blockIdx.y * CW + wt;
    const int h0  = seg * SEGH;

    const float2* __restrict__ base = in2 + (size_t)(b * NH) * NW + w;

    // Batched loads (MLP=32): one float2 per row carries both channels.
    float2 v[SEGH];
    #pragma unroll
    for (int u = 0; u < SEGH; ++u)
        v[u] = base[(size_t)(h0 + u) * NW];

    int last0 = -32768, last1 = -32768;
    int first0 = 20000, first1 = 20000;
    #pragma unroll
    for (int u = 0; u < SEGH; ++u) {
        int h = h0 + u;
        if ((1.0f - v[u].x) * 127.5f < 1.0f) {
            last0 = h;
            if (first0 == 20000) first0 = h;
        }
        sL0[h][wt] = (short)last0;
        if ((1.0f - v[u].y) * 127.5f < 1.0f) {
            last1 = h;
            if (first1 == 20000) first1 = h;
        }
        sL1[h][wt] = (short)last1;
    }
    segLast[0][seg][wt]  = (short)last0;
    segLast[1][seg][wt]  = (short)last1;
    segFirst[0][seg][wt] = (short)first0;
    segFirst[1][seg][wt] = (short)first1;
    __syncthreads();

    // Cross-segment prefix(max of last) / suffix(min of first), both channels.
    if (seg == 0) {
        #pragma unroll
        for (int c = 0; c < 2; ++c) {
            int acc = -32768;
            #pragma unroll
            for (int s = 0; s < NSEG; ++s) {
                incLast[c][s][wt] = (short)acc;
                acc = max(acc, (int)segLast[c][s][wt]);
            }
            int acc2 = 20000;
            #pragma unroll
            for (int s = NSEG - 1; s >= 0; --s) {
                incNxt[c][s][wt] = (short)acc2;
                acc2 = min(acc2, (int)segFirst[c][s][wt]);
            }
        }
    }
    __syncthreads();

    // Backward scan within segment; interleaved float2 store.
    float2* __restrict__ sc = g2_scratch2 + (size_t)(b * NH) * NW + w;
    const int inc0 = incLast[0][seg][wt];
    const int inc1 = incLast[1][seg][wt];
    int nxt0 = incNxt[0][seg][wt];
    int nxt1 = incNxt[1][seg][wt];
    #pragma unroll
    for (int u = SEGH - 1; u >= 0; --u) {
        int h = h0 + u;
        int lv0 = max((int)sL0[h][wt], inc0);
        if (lv0 == h) nxt0 = h;
        float g0 = (float)min(h - lv0, nxt0 - h);
        int lv1 = max((int)sL1[h][wt], inc1);
        if (lv1 == h) nxt1 = h;
        float g1 = (float)min(h - lv1, nxt1 - h);
        sc[(size_t)h * NW] = make_float2(g0 * g0, g1 * g1);
    }
}

// -------------------------------------------------------------------------
// Kernel 2: row pass, warp-uniform broadcast windows.
// One block per (b,h) row, 320 threads (10 warps). Each warp scans a uniform
// clamped 64-column window (32 float4 chunks; chunk = 2 cols x 2 channels,
// all LDS addresses warp-uniform -> broadcast). Rare tail handled by a
// warp-uniform ballot-gated expansion using the exact per-lane bound.
// -------------------------------------------------------------------------
#define NF4  (NW / 2)    // 160 two-column chunks
#define WCHK 32          // window chunks per warp (64 columns)

__global__ void __launch_bounds__(NW) row_pass_kernel(float* __restrict__ out) {
    const int bh = blockIdx.x;            // b*320 + h
    const int j  = threadIdx.x;
    const int b  = bh / NH;
    const int h  = bh - b * NH;

    __shared__ __align__(16) float2 sh2[NW];

    sh2[j] = g2_scratch2[((size_t)(b * NH) + h) * NW + j];
    __syncthreads();

    const float4* __restrict__ v4 = (const float4*)sh2;  // [NF4]

    const float fj = (float)j;
    const int jb = j & ~31;               // warp's first pixel

    // Clamped warp-uniform window of WCHK chunks around the warp's 16 own chunks.
    int fs = (jb >> 1) - 8;
    if (fs < 0) fs = 0;
    if (fs > NF4 - WCHK) fs = NF4 - WCHK;

    float m0 = 3e38f, m1 = 3e38f;
    const float dbase = fj - (float)(2 * fs);

    #pragma unroll
    for (int s = 0; s < WCHK; ++s) {
        float4 a = v4[fs + s];            // broadcast LDS.128
        float d0 = dbase - (float)(2 * s);
        float d1 = d0 - 1.0f;
        float r0 = fmaf(d0, d0, a.x);
        float r1 = fmaf(d1, d1, a.z);
        m0 = fminf(m0, fminf(r0, r1));
        float r2 = fmaf(d0, d0, a.y);
        float r3 = fmaf(d1, d1, a.w);
        m1 = fminf(m1, fminf(r2, r3));
    }

    // Warp-uniform exact expansion beyond the window (~0.2% of pixels).
    {
        int tl = fs - 1;
        int tr = fs + WCHK;
        for (;;) {
            float mM = fmaxf(m0, m1);
            float dL = fj - (float)(2 * tl + 1);
            float dR = (float)(2 * tr) - fj;
            bool nL = (tl >= 0)   && (dL * dL <= mM);
            bool nR = (tr < NF4)  && (dR * dR <= mM);
            unsigned bL = __ballot_sync(0xffffffffu, nL);
            unsigned bR = __ballot_sync(0xffffffffu, nR);
            if (!(bL | bR)) break;
            if (bL) {
                float4 a = v4[tl];
                float d0 = fj - (float)(2 * tl);
                float d1 = d0 - 1.0f;
                m0 = fminf(m0, fminf(fmaf(d0, d0, a.x), fmaf(d1, d1, a.z)));
                m1 = fminf(m1, fminf(fmaf(d0, d0, a.y), fmaf(d1, d1, a.w)));
                --tl;
            }
            if (bR) {
                float4 a = v4[tr];
                float d0 = fj - (float)(2 * tr);
                float d1 = d0 - 1.0f;
                m0 = fminf(m0, fminf(fmaf(d0, d0, a.x), fmaf(d1, d1, a.z)));
                m1 = fminf(m1, fminf(fmaf(d0, d0, a.y), fmaf(d1, d1, a.w)));
                ++tr;
            }
        }
    }

    // sigmas = [0.02,0.08,0.16]*320 -> 2*sigma^2 = [81.92, 1310.72, 5242.88]
    const float inv0 = 1.0f / 81.92f;
    const float inv1 = 1.0f / 1310.72f;
    const float inv2 = 1.0f / 5242.88f;

    float* __restrict__ o = out + ((size_t)bh * NW + j) * 6;
    float2 p0 = make_float2(__expf(-m0 * inv0), __expf(-m0 * inv1));
    float2 p1 = make_float2(__expf(-m0 * inv2), __expf(-m1 * inv0));
    float2 p2 = make_float2(__expf(-m1 * inv1), __expf(-m1 * inv2));
    ((float2*)o)[0] = p0;
    ((float2*)o)[1] = p1;
    ((float2*)o)[2] = p2;
}

extern "C" void kernel_launch(void* const* d_in, const int* in_sizes, int n_in,
                              void* d_out, int out_size) {
    const float2* in2 = (const float2*)d_in[0];
    float* out = (float*)d_out;
    (void)in_sizes; (void)n_in; (void)out_size;

    dim3 g1(NB, NW / CW);
    dim3 b1(CW, NSEG);
    col_pass_kernel<<<g1, b1>>>(in2);
    row_pass_kernel<<<NB * NH, NW>>>(out);
}

// round 12
// speedup vs baseline: 1.3683x; 1.3683x over previous
#include <cuda_runtime.h>

// inputs [4,320,320,2] f32 -> output [4,320,320,6] f32
#define NB   4
#define NH   320
#define NW   320
#define NIMG 8

// Scratch: per-image squared 1D column distances g2[img][h][w].
__device__ float g2_scratch[NIMG * NH * NW];

// -------------------------------------------------------------------------
// Kernel 1: column pass, segmented (R6 winner, unchanged).
// grid (NIMG, NW/32), block (32, 10): 32 columns x 10 row-segments of 32.
// Sentinels (-32768 / 20000) give g^2 >= 4e8: exp underflows to exactly 0
// for all sigmas and can never beat a real candidate -> matches BIG=1e5.
// -------------------------------------------------------------------------
#define CW   32
#define NSEG 10
#define SEGH 32

__global__ void __launch_bounds__(CW * NSEG) col_pass_kernel(const float* __restrict__ in) {
    __shared__ short smLast[NH][CW];      // 20 KB
    __shared__ short segLast[NSEG][CW];
    __shared__ short segFirst[NSEG][CW];
    __shared__ short incLast[NSEG][CW];
    __shared__ short incNxt[NSEG][CW];

    const int img = blockIdx.x;           // 0..7
    const int b   = img >> 1;
    const int c   = img & 1;
    const int wt  = threadIdx.x;          // 0..31
    const int seg = threadIdx.y;          // 0..9
    const int w   = blockIdx.y * CW + wt;
    const int h0  = seg * SEGH;

    const float* __restrict__ base = in + (((size_t)b * NH) * NW + w) * 2 + c;

    float v[SEGH];
    #pragma unroll
    for (int u = 0; u < SEGH; ++u)
        v[u] = base[(size_t)(h0 + u) * (NW * 2)];

    int last = -32768, first = 20000;
    #pragma unroll
    for (int u = 0; u < SEGH; ++u) {
        int h = h0 + u;
        if ((1.0f - v[u]) * 127.5f < 1.0f) {
            last = h;
            if (first == 20000) first = h;
        }
        smLast[h][wt] = (short)last;
    }
    segLast[seg][wt]  = (short)last;
    segFirst[seg][wt] = (short)first;
    __syncthreads();

    if (seg == 0) {
        int acc = -32768;
        #pragma unroll
        for (int s = 0; s < NSEG; ++s) {
            incLast[s][wt] = (short)acc;
            acc = max(acc, (int)segLast[s][wt]);
        }
        int acc2 = 20000;
        #pragma unroll
        for (int s = NSEG - 1; s >= 0; --s) {
            incNxt[s][wt] = (short)acc2;
            acc2 = min(acc2, (int)segFirst[s][wt]);
        }
    }
    __syncthreads();

    float* __restrict__ sc = g2_scratch + (size_t)img * NH * NW + w;
    const int inc = incLast[seg][wt];
    int nxt = incNxt[seg][wt];
    #pragma unroll
    for (int u = SEGH - 1; u >= 0; --u) {
        int h = h0 + u;
        int lastv = max((int)smLast[h][wt], inc);
        if (lastv == h) nxt = h;
        float g = (float)min(h - lastv, nxt - h);
        sc[(size_t)h * NW] = g * g;
    }
}

// -------------------------------------------------------------------------
// Kernel 2: row pass. One thread per pixel j, both channels. Per-thread
// clamped 9-tile (36-col) window + exact pruned expansion beyond it.
// Epilogue: ONE __expf per channel; other two sigmas recovered by powering
// (denoms are exact powers: 81.92*16 = 1310.72, *4 = 5242.88).
//   e3 = exp(-m/5242.88);  e2 = e3^4 (2 squarings);  e1 = e2^16 (4 squarings)
// grid NB*NH, block 320.
// -------------------------------------------------------------------------
#define NT4  (NW / 4)   // 80 four-wide tiles
#define WTIL 9          // window tiles (covers >= +-16 columns around j)

__global__ void __launch_bounds__(NW) row_pass_kernel(float* __restrict__ out) {
    const int bh = blockIdx.x;            // b*320 + h
    const int j  = threadIdx.x;
    const int b  = bh / NH;
    const int h  = bh - b * NH;

    __shared__ __align__(16) float sh0[NW];
    __shared__ __align__(16) float sh1[NW];

    sh0[j] = g2_scratch[(((size_t)(b * 2 + 0) * NH) + h) * NW + j];
    sh1[j] = g2_scratch[(((size_t)(b * 2 + 1) * NH) + h) * NW + j];
    __syncthreads();

    const float4* __restrict__ v0 = (const float4*)sh0;
    const float4* __restrict__ v1 = (const float4*)sh1;

    const float fj = (float)j;
    float m0 = 3e38f, m1 = 3e38f;

    auto evalTile4 = [&](int tb) {
        float4 a = v0[tb];
        float4 c = v1[tb];
        float d0 = fj - (float)(tb * 4);
        float d1 = d0 - 1.0f, d2 = d0 - 2.0f, d3 = d0 - 3.0f;
        float r0 = fmaf(d0, d0, a.x), r1 = fmaf(d1, d1, a.y);
        float r2 = fmaf(d2, d2, a.z), r3 = fmaf(d3, d3, a.w);
        m0 = fminf(m0, fminf(fminf(r0, r1), fminf(r2, r3)));
        float s0 = fmaf(d0, d0, c.x), s1 = fmaf(d1, d1, c.y);
        float s2 = fmaf(d2, d2, c.z), s3 = fmaf(d3, d3, c.w);
        m1 = fminf(m1, fminf(fminf(s0, s1), fminf(s2, s3)));
    };

    // Clamped window of WTIL aligned 4-wide tiles centered on j's tile.
    const int tb0 = j >> 2;
    int ws = tb0 - (WTIL / 2);
    if (ws < 0) ws = 0;
    if (ws > NT4 - WTIL) ws = NT4 - WTIL;

    #pragma unroll
    for (int s = 0; s < WTIL; ++s)
        evalTile4(ws + s);

    // Exact fallback expansion beyond the window (rare).
    {
        int tl = ws - 1;
        int tr = ws + WTIL;
        float dL = fj - (float)(4 * tl + 3);  // min distance into left tile
        float dR = (float)(4 * tr) - fj;      // min distance into right tile

        for (;;) {
            float mM = fmaxf(m0, m1);
            bool needL = (tl >= 0)   && (dL * dL <= mM);
            bool needR = (tr < NT4)  && (dR * dR <= mM);
            if (!(needL || needR)) break;
            if (needL) { evalTile4(tl); --tl; dL += 4.0f; }
            if (needR) { evalTile4(tr); ++tr; dR += 4.0f; }
        }
    }

    // Epilogue: e3 = exp(-m/5242.88); e2 = e3^4; e1 = e2^16.
    const float inv2 = 1.0f / 5242.88f;

    float e3a = __expf(-m0 * inv2);
    float sa  = e3a * e3a;
    float e2a = sa * sa;                 // e3a^4  = exp(-m0/1310.72)
    float pa  = e2a * e2a;               // e2a^2
    float qa  = pa * pa;                 // e2a^4
    float ra  = qa * qa;                 // e2a^8
    float e1a = ra * ra;                 // e2a^16 = exp(-m0/81.92)

    float e3b = __expf(-m1 * inv2);
    float sb  = e3b * e3b;
    float e2b = sb * sb;
    float pb  = e2b * e2b;
    float qb  = pb * pb;
    float rb  = qb * qb;
    float e1b = rb * rb;

    float* __restrict__ o = out + ((size_t)bh * NW + j) * 6;
    ((float2*)o)[0] = make_float2(e1a, e2a);
    ((float2*)o)[1] = make_float2(e3a, e1b);
    ((float2*)o)[2] = make_float2(e2b, e3b);
}

extern "C" void kernel_launch(void* const* d_in, const int* in_sizes, int n_in,
                              void* d_out, int out_size) {
    const float* in = (const float*)d_in[0];
    float* out = (float*)d_out;
    (void)in_sizes; (void)n_in; (void)out_size;

    dim3 g1(NIMG, NW / CW);
    dim3 b1(CW, NSEG);
    col_pass_kernel<<<g1, b1>>>(in);
    row_pass_kernel<<<NB * NH, NW>>>(out);
}